// round 13
// baseline (speedup 1.0000x reference)
#include <cuda_runtime.h>
#include <cuda_bf16.h>
#include <cstdint>

#define NUM_GRAPHS 16384
#define C 128
#define C2 256

// Scratch (static device globals — no allocation in kernel_launch)
__device__ int            g_offs[NUM_GRAPHS + 1];
__device__ __nv_bfloat16  g_pA_hi[(size_t)NUM_GRAPHS * C];   // pooled hi, 4 MB
__device__ __nv_bfloat16  g_pA_lo[(size_t)NUM_GRAPHS * C];   // pooled lo, 4 MB
__device__ __nv_bfloat16  g_wt_hi[C2 * C];                   // W^T hi [256][128]
__device__ __nv_bfloat16  g_wt_lo[C2 * C];                   // W^T lo

// ---------------------------------------------------------------------------
// Kernel 0: segment offsets via vectorized coalesced boundary scan.
// Dtype-robust: JAX x64-disabled stores "int64" as int32; probe an odd 32-bit
// word (int64 high word == 0, int32 late id > 0).
// ---------------------------------------------------------------------------
__global__ void seg_offsets_kernel(const int* __restrict__ batch32, int n) {
    int tid  = blockIdx.x * blockDim.x + threadIdx.x;
    int base = tid * 4;
    if (base >= n) return;

    int probe_idx = ((n - 1) & 1) ? (n - 1) : (n - 2);   // odd index < n
    bool is_i32 = (probe_idx >= 1) && (__ldg(&batch32[probe_idx]) != 0);

    int c[5];
    if (is_i32) {
        if (base + 4 <= n) {
            int4 q = *reinterpret_cast<const int4*>(batch32 + base);
            c[0] = q.x; c[1] = q.y; c[2] = q.z; c[3] = q.w;
        } else {
            #pragma unroll
            for (int k = 0; k < 4; ++k)
                c[k] = (base + k < n) ? batch32[base + k] : NUM_GRAPHS;
        }
        c[4] = (base + 4 < n) ? batch32[base + 4] : NUM_GRAPHS;
    } else {
        #pragma unroll
        for (int k = 0; k < 5; ++k)
            c[k] = (base + k < n) ? batch32[2 * (base + k)] : NUM_GRAPHS;
    }

    if (base == 0) {
        for (int g = 0; g <= c[0]; ++g) g_offs[g] = 0;
    }
    #pragma unroll
    for (int k = 0; k < 4; ++k) {
        int j = base + k;
        if (j >= n) break;
        for (int g = c[k] + 1; g <= c[k + 1]; ++g) g_offs[g] = j + 1;
    }
}

// ---------------------------------------------------------------------------
// Kernel 0b: W^T bf16 hi/lo split. g_wt[n*128+k] = bf16split(W[k][n]).
// ---------------------------------------------------------------------------
__global__ void pack_w_kernel(const float* __restrict__ nn_w) {
    int p = blockIdx.x * 256 + threadIdx.x;   // 0..32767
    int n = p >> 7;
    int k = p & 127;
    float w = nn_w[k * C2 + n];
    __nv_bfloat16 hi = __float2bfloat16(w);
    __nv_bfloat16 lo = __float2bfloat16(w - __bfloat162float(hi));
    g_wt_hi[p] = hi;
    g_wt_lo[p] = lo;
}

// ---------------------------------------------------------------------------
// Kernel 1: fused gate + online segment-softmax + weighted pooling.
// One warp per graph, lane = 4 channels (float4). 4 rows per group with
// explicit prefetch; merged 4-sum reduction (10 SHFL). Output: bf16 hi/lo.
// (At HBM ceiling: 76% DRAM, ~6 TB/s.)
// ---------------------------------------------------------------------------
__device__ __forceinline__ void store_bf16x4(__nv_bfloat16* dst, float4 v) {
    __nv_bfloat16 bx = __float2bfloat16(v.x);
    __nv_bfloat16 by = __float2bfloat16(v.y);
    __nv_bfloat16 bz = __float2bfloat16(v.z);
    __nv_bfloat16 bw = __float2bfloat16(v.w);
    uint2 pk;
    pk.x = (uint32_t)__bfloat16_as_ushort(bx) | ((uint32_t)__bfloat16_as_ushort(by) << 16);
    pk.y = (uint32_t)__bfloat16_as_ushort(bz) | ((uint32_t)__bfloat16_as_ushort(bw) << 16);
    *reinterpret_cast<uint2*>(dst) = pk;
}

__global__ __launch_bounds__(256) void pool_kernel(
    const float4* __restrict__ x4,        // [N, 32] float4 view of [N,128]
    const float4* __restrict__ gate_w4,   // [32] float4 view of [128]
    const float*  __restrict__ gate_b)    // [1]
{
    const int warp = threadIdx.x >> 5;
    const int lane = threadIdx.x & 31;
    const int g = blockIdx.x * 8 + warp;

    const int lo = g_offs[g];
    const int hi = g_offs[g + 1];

    __nv_bfloat16* out_hi = g_pA_hi + (size_t)g * C + lane * 4;
    __nv_bfloat16* out_lo = g_pA_lo + (size_t)g * C + lane * 4;

    if (lo >= hi) {
        float4 z = make_float4(0.f, 0.f, 0.f, 0.f);
        store_bf16x4(out_hi, z);
        store_bf16x4(out_lo, z);
        return;
    }

    const float4 gw = gate_w4[lane];
    const float  gb = gate_b[0];

    float  m = -INFINITY;
    float  s = 0.0f;
    float4 acc = make_float4(0.f, 0.f, 0.f, 0.f);

    const int last = hi - 1;

    float4 v0 = x4[(size_t)lo * 32 + lane];
    float4 v1 = x4[(size_t)min(lo + 1, last) * 32 + lane];
    float4 v2 = x4[(size_t)min(lo + 2, last) * 32 + lane];
    float4 v3 = x4[(size_t)min(lo + 3, last) * 32 + lane];

    for (int r = lo; r < hi; r += 4) {
        int rn = r + 4;
        float4 n0 = x4[(size_t)min(rn + 0, last) * 32 + lane];
        float4 n1 = x4[(size_t)min(rn + 1, last) * 32 + lane];
        float4 n2 = x4[(size_t)min(rn + 2, last) * 32 + lane];
        float4 n3 = x4[(size_t)min(rn + 3, last) * 32 + lane];

        float p0 = v0.x*gw.x + v0.y*gw.y + v0.z*gw.z + v0.w*gw.w;
        float p1 = v1.x*gw.x + v1.y*gw.y + v1.z*gw.z + v1.w*gw.w;
        float p2 = v2.x*gw.x + v2.y*gw.y + v2.z*gw.z + v2.w*gw.w;
        float p3 = v3.x*gw.x + v3.y*gw.y + v3.z*gw.z + v3.w*gw.w;

        // merged 4-sum warp reduction (10 SHFL total)
        float ua = (lane & 1) ? p1 : p0;
        float ub = (lane & 1) ? p0 : p1;
        ua += __shfl_xor_sync(0xffffffffu, ub, 1);
        float va = (lane & 1) ? p3 : p2;
        float vb = (lane & 1) ? p2 : p3;
        va += __shfl_xor_sync(0xffffffffu, vb, 1);
        float wa = (lane & 2) ? va : ua;
        float wb = (lane & 2) ? ua : va;
        wa += __shfl_xor_sync(0xffffffffu, wb, 2);
        wa += __shfl_xor_sync(0xffffffffu, wa, 4);
        wa += __shfl_xor_sync(0xffffffffu, wa, 8);
        wa += __shfl_xor_sync(0xffffffffu, wa, 16);
        float s0 = __shfl_sync(0xffffffffu, wa, 0) + gb;
        float s1 = __shfl_sync(0xffffffffu, wa, 1) + gb;
        float s2 = __shfl_sync(0xffffffffu, wa, 2) + gb;
        float s3 = __shfl_sync(0xffffffffu, wa, 3) + gb;

        if (r + 1 >= hi) s1 = -INFINITY;
        if (r + 2 >= hi) s2 = -INFINITY;
        if (r + 3 >= hi) s3 = -INFINITY;

        float mg    = fmaxf(fmaxf(s0, s1), fmaxf(s2, s3));
        float m_new = fmaxf(m, mg);
        float alpha = __expf(m - m_new);
        float e0 = __expf(s0 - m_new);
        float e1 = __expf(s1 - m_new);
        float e2 = __expf(s2 - m_new);
        float e3 = __expf(s3 - m_new);

        s = fmaf(s, alpha, (e0 + e1) + (e2 + e3));
        acc.x = fmaf(acc.x, alpha, fmaf(e1, v1.x, e0 * v0.x) + fmaf(e3, v3.x, e2 * v2.x));
        acc.y = fmaf(acc.y, alpha, fmaf(e1, v1.y, e0 * v0.y) + fmaf(e3, v3.y, e2 * v2.y));
        acc.z = fmaf(acc.z, alpha, fmaf(e1, v1.z, e0 * v0.z) + fmaf(e3, v3.z, e2 * v2.z));
        acc.w = fmaf(acc.w, alpha, fmaf(e1, v1.w, e0 * v0.w) + fmaf(e3, v3.w, e2 * v2.w));
        m = m_new;

        v0 = n0; v1 = n1; v2 = n2; v3 = n3;
    }

    float inv = __frcp_rn(s);
    float4 pv;
    pv.x = acc.x * inv;
    pv.y = acc.y * inv;
    pv.z = acc.z * inv;
    pv.w = acc.w * inv;

    // bf16 hi/lo split
    float4 hv, lv;
    hv.x = __bfloat162float(__float2bfloat16(pv.x)); lv.x = pv.x - hv.x;
    hv.y = __bfloat162float(__float2bfloat16(pv.y)); lv.y = pv.y - hv.y;
    hv.z = __bfloat162float(__float2bfloat16(pv.z)); lv.z = pv.z - hv.z;
    hv.w = __bfloat162float(__float2bfloat16(pv.w)); lv.w = pv.w - hv.w;
    store_bf16x4(out_hi, hv);
    store_bf16x4(out_lo, lv);
}

// ---------------------------------------------------------------------------
// Kernel 2: out = pooled @ W + b via warp-level HMMA (mma.sync m16n8k16,
// bf16x3: D = Ah*Bh + Ah*Bl + Al*Bh). Baseline sm_80+ PTX — compiles at
// target sm_103 (tcgen05 needs the 'a' target the harness doesn't use).
// 512 blocks x 8 warps; warp = 16 graphs x 64 cols, K=128 (8 k-tiles).
// B frags are block-shared -> L1-hot. Fragment layout: standard PTX
// (groupID = lane>>2, tig = lane&3), all loads 4B-aligned k-pairs.
// ---------------------------------------------------------------------------
__device__ __forceinline__ uint32_t ld_bf2(const __nv_bfloat16* p) {
    return *reinterpret_cast<const uint32_t*>(p);
}

__device__ __forceinline__ void mma_16816(float* d, uint32_t a0, uint32_t a1,
                                          uint32_t a2, uint32_t a3,
                                          uint32_t b0, uint32_t b1) {
    asm volatile(
        "mma.sync.aligned.m16n8k16.row.col.f32.bf16.bf16.f32 "
        "{%0,%1,%2,%3}, {%4,%5,%6,%7}, {%8,%9}, {%0,%1,%2,%3};"
        : "+f"(d[0]), "+f"(d[1]), "+f"(d[2]), "+f"(d[3])
        : "r"(a0), "r"(a1), "r"(a2), "r"(a3), "r"(b0), "r"(b1));
}

__global__ __launch_bounds__(256) void gemm_hmma_kernel(
    const float* __restrict__ nn_b,   // [256]
    float* __restrict__ out)          // [16384, 256]
{
    const int warp = threadIdx.x >> 5;
    const int lane = threadIdx.x & 31;
    const int gid  = lane >> 2;           // groupID (0..7)
    const int tig  = lane & 3;            // thread-in-group

    const int bx   = blockIdx.x;
    const int gblk = (bx >> 2) * 128;     // block: 128 graphs
    const int n0   = (bx & 3) * 64;       // block: 64 cols
    const int g0   = gblk + warp * 16;    // warp: 16 graphs

    const size_t rA0 = (size_t)(g0 + gid) * C;      // A row (lower 8)
    const size_t rA8 = (size_t)(g0 + gid + 8) * C;  // A row (upper 8)
    const int ko = 2 * tig;

    float acc[8][4];
    #pragma unroll
    for (int j = 0; j < 8; ++j)
        #pragma unroll
        for (int c = 0; c < 4; ++c) acc[j][c] = 0.0f;

    #pragma unroll
    for (int kt = 0; kt < 8; ++kt) {
        const int k0 = kt * 16;

        uint32_t aH0 = ld_bf2(g_pA_hi + rA0 + k0 + ko);
        uint32_t aH1 = ld_bf2(g_pA_hi + rA8 + k0 + ko);
        uint32_t aH2 = ld_bf2(g_pA_hi + rA0 + k0 + 8 + ko);
        uint32_t aH3 = ld_bf2(g_pA_hi + rA8 + k0 + 8 + ko);
        uint32_t aL0 = ld_bf2(g_pA_lo + rA0 + k0 + ko);
        uint32_t aL1 = ld_bf2(g_pA_lo + rA8 + k0 + ko);
        uint32_t aL2 = ld_bf2(g_pA_lo + rA0 + k0 + 8 + ko);
        uint32_t aL3 = ld_bf2(g_pA_lo + rA8 + k0 + 8 + ko);

        #pragma unroll
        for (int j = 0; j < 8; ++j) {
            const int nrow = (n0 + j * 8 + gid) * C;   // W^T row = output col
            uint32_t bH0 = ld_bf2(g_wt_hi + nrow + k0 + ko);
            uint32_t bH1 = ld_bf2(g_wt_hi + nrow + k0 + 8 + ko);
            uint32_t bL0 = ld_bf2(g_wt_lo + nrow + k0 + ko);
            uint32_t bL1 = ld_bf2(g_wt_lo + nrow + k0 + 8 + ko);

            mma_16816(acc[j], aH0, aH1, aH2, aH3, bH0, bH1);
            mma_16816(acc[j], aH0, aH1, aH2, aH3, bL0, bL1);
            mma_16816(acc[j], aL0, aL1, aL2, aL3, bH0, bH1);
        }
    }

    // epilogue: rows g0+gid and g0+gid+8, cols n0 + j*8 + 2*tig (+1)
    const int row0 = g0 + gid;
    const int row8 = g0 + gid + 8;
    const bool ne0 = g_offs[row0 + 1] > g_offs[row0];
    const bool ne8 = g_offs[row8 + 1] > g_offs[row8];
    float* o0 = out + (size_t)row0 * C2;
    float* o8 = out + (size_t)row8 * C2;

    #pragma unroll
    for (int j = 0; j < 8; ++j) {
        int col = n0 + j * 8 + ko;
        float2 bias = *reinterpret_cast<const float2*>(nn_b + col);
        float2 lo2, hi2;
        lo2.x = ne0 ? (acc[j][0] + bias.x) : 0.0f;
        lo2.y = ne0 ? (acc[j][1] + bias.y) : 0.0f;
        hi2.x = ne8 ? (acc[j][2] + bias.x) : 0.0f;
        hi2.y = ne8 ? (acc[j][3] + bias.y) : 0.0f;
        *reinterpret_cast<float2*>(o0 + col) = lo2;
        *reinterpret_cast<float2*>(o8 + col) = hi2;
    }
}

// ---------------------------------------------------------------------------
// kernel_launch
// Inputs (metadata order): x [N,128] f32, batch [N] (int32 on device), gate_w,
//                          gate_b, nn_w [128,256] f32, nn_b [256] f32
// Output: [16384, 256] f32
// 4 launches (seg, pack, pool, gemm): ncu's captured launch (#6 global, after
// 2 harness prefix launches) lands on gemm_hmma_kernel.
// ---------------------------------------------------------------------------
extern "C" void kernel_launch(void* const* d_in, const int* in_sizes, int n_in,
                              void* d_out, int out_size) {
    const float* x      = (const float*)d_in[0];
    const int*   batch  = (const int*)d_in[1];
    const float* gate_w = (const float*)d_in[2];
    const float* gate_b = (const float*)d_in[3];
    const float* nn_w   = (const float*)d_in[4];
    const float* nn_b   = (const float*)d_in[5];
    float*       out    = (float*)d_out;

    const int N = in_sizes[1];   // number of nodes

    int seg_threads = (N + 3) / 4;
    seg_offsets_kernel<<<(seg_threads + 255) / 256, 256>>>(batch, N);
    pack_w_kernel<<<128, 256>>>(nn_w);
    pool_kernel<<<NUM_GRAPHS / 8, 256>>>(
        reinterpret_cast<const float4*>(x),
        reinterpret_cast<const float4*>(gate_w),
        gate_b);
    gemm_hmma_kernel<<<512, 256>>>(nn_b, out);
}

// round 14
// speedup vs baseline: 1.2090x; 1.2090x over previous
#include <cuda_runtime.h>
#include <cuda_bf16.h>
#include <cstdint>

#define NUM_GRAPHS 16384
#define C 128
#define C2 256

// Scratch (static device globals — no allocation in kernel_launch)
__device__ int       g_offs[NUM_GRAPHS + 1];
// A fragments: [gtile(1024)][kt(8)][lane(32)][reg(4)] uint32 (bf16 pair) = 4 MB each
__device__ uint32_t  g_pA_fh[1024 * 8 * 32 * 4];
__device__ uint32_t  g_pA_fl[1024 * 8 * 32 * 4];
// B fragments: [j(32)][kt(8)][lane(32)] uint2 (b0,b1 bf16 pairs) = 64 KB each
__device__ uint2     g_wt_fh[32 * 8 * 32];
__device__ uint2     g_wt_fl[32 * 8 * 32];

// ---------------------------------------------------------------------------
// Kernel 0: segment offsets via vectorized coalesced boundary scan.
// Dtype-robust: JAX x64-disabled stores "int64" as int32; probe an odd 32-bit
// word (int64 high word == 0, int32 late id > 0).
// ---------------------------------------------------------------------------
__global__ void seg_offsets_kernel(const int* __restrict__ batch32, int n) {
    int tid  = blockIdx.x * blockDim.x + threadIdx.x;
    int base = tid * 4;
    if (base >= n) return;

    int probe_idx = ((n - 1) & 1) ? (n - 1) : (n - 2);   // odd index < n
    bool is_i32 = (probe_idx >= 1) && (__ldg(&batch32[probe_idx]) != 0);

    int c[5];
    if (is_i32) {
        if (base + 4 <= n) {
            int4 q = *reinterpret_cast<const int4*>(batch32 + base);
            c[0] = q.x; c[1] = q.y; c[2] = q.z; c[3] = q.w;
        } else {
            #pragma unroll
            for (int k = 0; k < 4; ++k)
                c[k] = (base + k < n) ? batch32[base + k] : NUM_GRAPHS;
        }
        c[4] = (base + 4 < n) ? batch32[base + 4] : NUM_GRAPHS;
    } else {
        #pragma unroll
        for (int k = 0; k < 5; ++k)
            c[k] = (base + k < n) ? batch32[2 * (base + k)] : NUM_GRAPHS;
    }

    if (base == 0) {
        for (int g = 0; g <= c[0]; ++g) g_offs[g] = 0;
    }
    #pragma unroll
    for (int k = 0; k < 4; ++k) {
        int j = base + k;
        if (j >= n) break;
        for (int g = c[k] + 1; g <= c[k + 1]; ++g) g_offs[g] = j + 1;
    }
}

// ---------------------------------------------------------------------------
// Kernel 0b: W^T bf16 hi/lo split, FRAGMENT-MAJOR.
// p = j*256 + kt*32 + lane; lane=(gid,tig). b0 = W[kt*16+2tig ..+1][j*8+gid],
// b1 = same +8 in k. hi/lo split per element.
// ---------------------------------------------------------------------------
__device__ __forceinline__ uint32_t bf16pair(float a, float b) {
    return (uint32_t)__bfloat16_as_ushort(__float2bfloat16(a))
         | ((uint32_t)__bfloat16_as_ushort(__float2bfloat16(b)) << 16);
}

__global__ void pack_w_kernel(const float* __restrict__ nn_w) {
    int p = blockIdx.x * 256 + threadIdx.x;   // 0..8191
    int j    = p >> 8;
    int kt   = (p >> 5) & 7;
    int lane = p & 31;
    int gid  = lane >> 2;
    int tig  = lane & 3;
    int n  = j * 8 + gid;
    int k0 = kt * 16 + 2 * tig;

    float w00 = nn_w[(k0    ) * C2 + n];
    float w01 = nn_w[(k0 + 1) * C2 + n];
    float w10 = nn_w[(k0 + 8) * C2 + n];
    float w11 = nn_w[(k0 + 9) * C2 + n];

    float h00 = __bfloat162float(__float2bfloat16(w00));
    float h01 = __bfloat162float(__float2bfloat16(w01));
    float h10 = __bfloat162float(__float2bfloat16(w10));
    float h11 = __bfloat162float(__float2bfloat16(w11));

    g_wt_fh[p] = make_uint2(bf16pair(h00, h01), bf16pair(h10, h11));
    g_wt_fl[p] = make_uint2(bf16pair(w00 - h00, w01 - h01),
                            bf16pair(w10 - h10, w11 - h11));
}

// ---------------------------------------------------------------------------
// Kernel 1: fused gate + online segment-softmax + weighted pooling.
// One warp per graph, lane = 4 channels. 4 rows per group with prefetch;
// merged 4-sum reduction (10 SHFL). Epilogue: bf16 hi/lo split written in
// FRAGMENT-MAJOR layout (4 scattered STG.32 per lane — epilogue only).
// (Main loop at HBM ceiling: 76% DRAM, ~6 TB/s.)
// ---------------------------------------------------------------------------
__global__ __launch_bounds__(256) void pool_kernel(
    const float4* __restrict__ x4,        // [N, 32] float4 view of [N,128]
    const float4* __restrict__ gate_w4,   // [32] float4 view of [128]
    const float*  __restrict__ gate_b)    // [1]
{
    const int warp = threadIdx.x >> 5;
    const int lane = threadIdx.x & 31;
    const int g = blockIdx.x * 8 + warp;

    const int lo = g_offs[g];
    const int hi = g_offs[g + 1];

    float4 pv = make_float4(0.f, 0.f, 0.f, 0.f);

    if (lo < hi) {
        const float4 gw = gate_w4[lane];
        const float  gb = gate_b[0];

        float  m = -INFINITY;
        float  s = 0.0f;
        float4 acc = make_float4(0.f, 0.f, 0.f, 0.f);

        const int last = hi - 1;

        float4 v0 = x4[(size_t)lo * 32 + lane];
        float4 v1 = x4[(size_t)min(lo + 1, last) * 32 + lane];
        float4 v2 = x4[(size_t)min(lo + 2, last) * 32 + lane];
        float4 v3 = x4[(size_t)min(lo + 3, last) * 32 + lane];

        for (int r = lo; r < hi; r += 4) {
            int rn = r + 4;
            float4 n0 = x4[(size_t)min(rn + 0, last) * 32 + lane];
            float4 n1 = x4[(size_t)min(rn + 1, last) * 32 + lane];
            float4 n2 = x4[(size_t)min(rn + 2, last) * 32 + lane];
            float4 n3 = x4[(size_t)min(rn + 3, last) * 32 + lane];

            float p0 = v0.x*gw.x + v0.y*gw.y + v0.z*gw.z + v0.w*gw.w;
            float p1 = v1.x*gw.x + v1.y*gw.y + v1.z*gw.z + v1.w*gw.w;
            float p2 = v2.x*gw.x + v2.y*gw.y + v2.z*gw.z + v2.w*gw.w;
            float p3 = v3.x*gw.x + v3.y*gw.y + v3.z*gw.z + v3.w*gw.w;

            // merged 4-sum warp reduction (10 SHFL total)
            float ua = (lane & 1) ? p1 : p0;
            float ub = (lane & 1) ? p0 : p1;
            ua += __shfl_xor_sync(0xffffffffu, ub, 1);
            float va = (lane & 1) ? p3 : p2;
            float vb = (lane & 1) ? p2 : p3;
            va += __shfl_xor_sync(0xffffffffu, vb, 1);
            float wa = (lane & 2) ? va : ua;
            float wb = (lane & 2) ? ua : va;
            wa += __shfl_xor_sync(0xffffffffu, wb, 2);
            wa += __shfl_xor_sync(0xffffffffu, wa, 4);
            wa += __shfl_xor_sync(0xffffffffu, wa, 8);
            wa += __shfl_xor_sync(0xffffffffu, wa, 16);
            float s0 = __shfl_sync(0xffffffffu, wa, 0) + gb;
            float s1 = __shfl_sync(0xffffffffu, wa, 1) + gb;
            float s2 = __shfl_sync(0xffffffffu, wa, 2) + gb;
            float s3 = __shfl_sync(0xffffffffu, wa, 3) + gb;

            if (r + 1 >= hi) s1 = -INFINITY;
            if (r + 2 >= hi) s2 = -INFINITY;
            if (r + 3 >= hi) s3 = -INFINITY;

            float mg    = fmaxf(fmaxf(s0, s1), fmaxf(s2, s3));
            float m_new = fmaxf(m, mg);
            float alpha = __expf(m - m_new);
            float e0 = __expf(s0 - m_new);
            float e1 = __expf(s1 - m_new);
            float e2 = __expf(s2 - m_new);
            float e3 = __expf(s3 - m_new);

            s = fmaf(s, alpha, (e0 + e1) + (e2 + e3));
            acc.x = fmaf(acc.x, alpha, fmaf(e1, v1.x, e0 * v0.x) + fmaf(e3, v3.x, e2 * v2.x));
            acc.y = fmaf(acc.y, alpha, fmaf(e1, v1.y, e0 * v0.y) + fmaf(e3, v3.y, e2 * v2.y));
            acc.z = fmaf(acc.z, alpha, fmaf(e1, v1.z, e0 * v0.z) + fmaf(e3, v3.z, e2 * v2.z));
            acc.w = fmaf(acc.w, alpha, fmaf(e1, v1.w, e0 * v0.w) + fmaf(e3, v3.w, e2 * v2.w));
            m = m_new;

            v0 = n0; v1 = n1; v2 = n2; v3 = n3;
        }

        float inv = __frcp_rn(s);
        pv.x = acc.x * inv;
        pv.y = acc.y * inv;
        pv.z = acc.z * inv;
        pv.w = acc.w * inv;
    }

    // bf16 hi/lo split
    float hx = __bfloat162float(__float2bfloat16(pv.x));
    float hy = __bfloat162float(__float2bfloat16(pv.y));
    float hz = __bfloat162float(__float2bfloat16(pv.z));
    float hw = __bfloat162float(__float2bfloat16(pv.w));
    uint32_t hp0 = bf16pair(hx, hy),        hp1 = bf16pair(hz, hw);
    uint32_t lp0 = bf16pair(pv.x - hx, pv.y - hy);
    uint32_t lp1 = bf16pair(pv.z - hz, pv.w - hw);

    // fragment-major scatter: pair p -> kt=p>>3, tig=(p&7)&3, half=(p&7)>>2
    const int gtile = g >> 4;
    const int r     = g & 15;
    const int rbase = (r & 7) * 4;
    const int reghi = r >> 3;
    #pragma unroll
    for (int q = 0; q < 2; ++q) {
        int p    = 2 * lane + q;
        int kt   = p >> 3;
        int pp   = p & 7;
        int tig  = pp & 3;
        int half = pp >> 2;
        int idx  = ((gtile * 8 + kt) * 32 + rbase + tig) * 4 + half * 2 + reghi;
        g_pA_fh[idx] = q ? hp1 : hp0;
        g_pA_fl[idx] = q ? lp1 : lp0;
    }
}

// ---------------------------------------------------------------------------
// Kernel 2: out = pooled @ W + b via HMMA (mma.sync m16n8k16 bf16x3), with
// FRAGMENT-MAJOR operands: A frags = 1 coalesced LDG.128 per (kt, hi/lo);
// B frags = 1 LDG.64 each, L1-resident (64 KB x2 total).
// 256 blocks x 8 warps; warp = 16 graphs x 128 cols (16 n8-tiles), K=128.
// ---------------------------------------------------------------------------
__device__ __forceinline__ void mma_16816(float* d, uint32_t a0, uint32_t a1,
                                          uint32_t a2, uint32_t a3,
                                          uint32_t b0, uint32_t b1) {
    asm volatile(
        "mma.sync.aligned.m16n8k16.row.col.f32.bf16.bf16.f32 "
        "{%0,%1,%2,%3}, {%4,%5,%6,%7}, {%8,%9}, {%0,%1,%2,%3};"
        : "+f"(d[0]), "+f"(d[1]), "+f"(d[2]), "+f"(d[3])
        : "r"(a0), "r"(a1), "r"(a2), "r"(a3), "r"(b0), "r"(b1));
}

__global__ __launch_bounds__(256) void gemm_hmma_kernel(
    const float* __restrict__ nn_b,   // [256]
    float* __restrict__ out)          // [16384, 256]
{
    const int warp  = threadIdx.x >> 5;
    const int lane  = threadIdx.x & 31;
    const int gid   = lane >> 2;
    const int tig   = lane & 3;
    const int gtile = (blockIdx.x >> 1) * 8 + warp;   // 16-graph tile
    const int jbase = (blockIdx.x & 1) * 16;          // 16 n8-tiles = 128 cols

    const uint4* Afh = reinterpret_cast<const uint4*>(g_pA_fh) + (size_t)gtile * 8 * 32 + lane;
    const uint4* Afl = reinterpret_cast<const uint4*>(g_pA_fl) + (size_t)gtile * 8 * 32 + lane;
    const uint2* Bfh = g_wt_fh + lane;
    const uint2* Bfl = g_wt_fl + lane;

    float acc[16][4];
    #pragma unroll
    for (int j = 0; j < 16; ++j)
        #pragma unroll
        for (int c = 0; c < 4; ++c) acc[j][c] = 0.0f;

    #pragma unroll
    for (int kt = 0; kt < 8; ++kt) {
        uint4 ah = Afh[kt * 32];          // a0..a3 hi (one LDG.128)
        uint4 al = Afl[kt * 32];          // a0..a3 lo

        #pragma unroll
        for (int j16 = 0; j16 < 16; ++j16) {
            int j = jbase + j16;
            uint2 bh = Bfh[(j * 8 + kt) * 32];
            uint2 bl = Bfl[(j * 8 + kt) * 32];
            mma_16816(acc[j16], ah.x, ah.y, ah.z, ah.w, bh.x, bh.y);
            mma_16816(acc[j16], ah.x, ah.y, ah.z, ah.w, bl.x, bl.y);
            mma_16816(acc[j16], al.x, al.y, al.z, al.w, bh.x, bh.y);
        }
    }

    // epilogue: rows gtile*16+gid (+8), cols (jbase+j16)*8 + 2*tig (+1)
    const int row0 = gtile * 16 + gid;
    const int row8 = row0 + 8;
    const bool ne0 = g_offs[row0 + 1] > g_offs[row0];
    const bool ne8 = g_offs[row8 + 1] > g_offs[row8];
    float* o0 = out + (size_t)row0 * C2;
    float* o8 = out + (size_t)row8 * C2;

    #pragma unroll
    for (int j16 = 0; j16 < 16; ++j16) {
        int col = (jbase + j16) * 8 + 2 * tig;
        float2 bias = *reinterpret_cast<const float2*>(nn_b + col);
        float2 lo2, hi2;
        lo2.x = ne0 ? (acc[j16][0] + bias.x) : 0.0f;
        lo2.y = ne0 ? (acc[j16][1] + bias.y) : 0.0f;
        hi2.x = ne8 ? (acc[j16][2] + bias.x) : 0.0f;
        hi2.y = ne8 ? (acc[j16][3] + bias.y) : 0.0f;
        *reinterpret_cast<float2*>(o0 + col) = lo2;
        *reinterpret_cast<float2*>(o8 + col) = hi2;
    }
}

// ---------------------------------------------------------------------------
// kernel_launch
// Inputs (metadata order): x [N,128] f32, batch [N] (int32 on device), gate_w,
//                          gate_b, nn_w [128,256] f32, nn_b [256] f32
// Output: [16384, 256] f32
// 4 launches (seg, pack, pool, gemm): ncu's captured launch lands on gemm.
// ---------------------------------------------------------------------------
extern "C" void kernel_launch(void* const* d_in, const int* in_sizes, int n_in,
                              void* d_out, int out_size) {
    const float* x      = (const float*)d_in[0];
    const int*   batch  = (const int*)d_in[1];
    const float* gate_w = (const float*)d_in[2];
    const float* gate_b = (const float*)d_in[3];
    const float* nn_w   = (const float*)d_in[4];
    const float* nn_b   = (const float*)d_in[5];
    float*       out    = (float*)d_out;

    const int N = in_sizes[1];   // number of nodes

    int seg_threads = (N + 3) / 4;
    seg_offsets_kernel<<<(seg_threads + 255) / 256, 256>>>(batch, N);
    pack_w_kernel<<<32, 256>>>(nn_w);
    pool_kernel<<<NUM_GRAPHS / 8, 256>>>(
        reinterpret_cast<const float4*>(x),
        reinterpret_cast<const float4*>(gate_w),
        gate_b);
    gemm_hmma_kernel<<<256, 256>>>(nn_b, out);
}

// round 15
// speedup vs baseline: 1.2707x; 1.0510x over previous
#include <cuda_runtime.h>
#include <cuda_bf16.h>
#include <cstdint>

#define NUM_GRAPHS 16384
#define C 128
#define C2 256

// Scratch (static device globals — no allocation in kernel_launch)
__device__ int       g_offs[NUM_GRAPHS + 1];
// A fragments: [gtile(1024)][kt(8)][lane(32)][reg(4)] uint32 (bf16 pair) = 4 MB each
__device__ uint32_t  g_pA_fh[1024 * 8 * 32 * 4];
__device__ uint32_t  g_pA_fl[1024 * 8 * 32 * 4];
// B fragments: [j(32)][kt(8)][lane(32)] uint2 (b0,b1 bf16 pairs) = 64 KB each
__device__ uint2     g_wt_fh[32 * 8 * 32];
__device__ uint2     g_wt_fl[32 * 8 * 32];

// ---------------------------------------------------------------------------
// Kernel 0: segment offsets via vectorized coalesced boundary scan.
// Dtype-robust: JAX x64-disabled stores "int64" as int32; probe an odd 32-bit
// word (int64 high word == 0, int32 late id > 0).
// ---------------------------------------------------------------------------
__global__ void seg_offsets_kernel(const int* __restrict__ batch32, int n) {
    int tid  = blockIdx.x * blockDim.x + threadIdx.x;
    int base = tid * 4;
    if (base >= n) return;

    int probe_idx = ((n - 1) & 1) ? (n - 1) : (n - 2);   // odd index < n
    bool is_i32 = (probe_idx >= 1) && (__ldg(&batch32[probe_idx]) != 0);

    int c[5];
    if (is_i32) {
        if (base + 4 <= n) {
            int4 q = *reinterpret_cast<const int4*>(batch32 + base);
            c[0] = q.x; c[1] = q.y; c[2] = q.z; c[3] = q.w;
        } else {
            #pragma unroll
            for (int k = 0; k < 4; ++k)
                c[k] = (base + k < n) ? batch32[base + k] : NUM_GRAPHS;
        }
        c[4] = (base + 4 < n) ? batch32[base + 4] : NUM_GRAPHS;
    } else {
        #pragma unroll
        for (int k = 0; k < 5; ++k)
            c[k] = (base + k < n) ? batch32[2 * (base + k)] : NUM_GRAPHS;
    }

    if (base == 0) {
        for (int g = 0; g <= c[0]; ++g) g_offs[g] = 0;
    }
    #pragma unroll
    for (int k = 0; k < 4; ++k) {
        int j = base + k;
        if (j >= n) break;
        for (int g = c[k] + 1; g <= c[k + 1]; ++g) g_offs[g] = j + 1;
    }
}

// ---------------------------------------------------------------------------
// Kernel 0b: W^T bf16 hi/lo split, FRAGMENT-MAJOR.
// p = j*256 + kt*32 + lane; lane=(gid,tig). b0 = W[kt*16+2tig ..+1][j*8+gid],
// b1 = same +8 in k. hi/lo split per element.
// ---------------------------------------------------------------------------
__device__ __forceinline__ uint32_t bf16pair(float a, float b) {
    return (uint32_t)__bfloat16_as_ushort(__float2bfloat16(a))
         | ((uint32_t)__bfloat16_as_ushort(__float2bfloat16(b)) << 16);
}

__global__ void pack_w_kernel(const float* __restrict__ nn_w) {
    int p = blockIdx.x * 256 + threadIdx.x;   // 0..8191
    int j    = p >> 8;
    int kt   = (p >> 5) & 7;
    int lane = p & 31;
    int gid  = lane >> 2;
    int tig  = lane & 3;
    int n  = j * 8 + gid;
    int k0 = kt * 16 + 2 * tig;

    float w00 = nn_w[(k0    ) * C2 + n];
    float w01 = nn_w[(k0 + 1) * C2 + n];
    float w10 = nn_w[(k0 + 8) * C2 + n];
    float w11 = nn_w[(k0 + 9) * C2 + n];

    float h00 = __bfloat162float(__float2bfloat16(w00));
    float h01 = __bfloat162float(__float2bfloat16(w01));
    float h10 = __bfloat162float(__float2bfloat16(w10));
    float h11 = __bfloat162float(__float2bfloat16(w11));

    g_wt_fh[p] = make_uint2(bf16pair(h00, h01), bf16pair(h10, h11));
    g_wt_fl[p] = make_uint2(bf16pair(w00 - h00, w01 - h01),
                            bf16pair(w10 - h10, w11 - h11));
}

// ---------------------------------------------------------------------------
// Kernel 1: fused gate + online segment-softmax + weighted pooling.
// One warp per graph, lane = 4 channels. 4 rows per group with prefetch;
// merged 4-sum reduction (10 SHFL). Epilogue: bf16 hi/lo split written in
// FRAGMENT-MAJOR layout. (Main loop at HBM ceiling: 76% DRAM, ~6 TB/s.)
// ---------------------------------------------------------------------------
__global__ __launch_bounds__(256) void pool_kernel(
    const float4* __restrict__ x4,        // [N, 32] float4 view of [N,128]
    const float4* __restrict__ gate_w4,   // [32] float4 view of [128]
    const float*  __restrict__ gate_b)    // [1]
{
    const int warp = threadIdx.x >> 5;
    const int lane = threadIdx.x & 31;
    const int g = blockIdx.x * 8 + warp;

    const int lo = g_offs[g];
    const int hi = g_offs[g + 1];

    float4 pv = make_float4(0.f, 0.f, 0.f, 0.f);

    if (lo < hi) {
        const float4 gw = gate_w4[lane];
        const float  gb = gate_b[0];

        float  m = -INFINITY;
        float  s = 0.0f;
        float4 acc = make_float4(0.f, 0.f, 0.f, 0.f);

        const int last = hi - 1;

        float4 v0 = x4[(size_t)lo * 32 + lane];
        float4 v1 = x4[(size_t)min(lo + 1, last) * 32 + lane];
        float4 v2 = x4[(size_t)min(lo + 2, last) * 32 + lane];
        float4 v3 = x4[(size_t)min(lo + 3, last) * 32 + lane];

        for (int r = lo; r < hi; r += 4) {
            int rn = r + 4;
            float4 n0 = x4[(size_t)min(rn + 0, last) * 32 + lane];
            float4 n1 = x4[(size_t)min(rn + 1, last) * 32 + lane];
            float4 n2 = x4[(size_t)min(rn + 2, last) * 32 + lane];
            float4 n3 = x4[(size_t)min(rn + 3, last) * 32 + lane];

            float p0 = v0.x*gw.x + v0.y*gw.y + v0.z*gw.z + v0.w*gw.w;
            float p1 = v1.x*gw.x + v1.y*gw.y + v1.z*gw.z + v1.w*gw.w;
            float p2 = v2.x*gw.x + v2.y*gw.y + v2.z*gw.z + v2.w*gw.w;
            float p3 = v3.x*gw.x + v3.y*gw.y + v3.z*gw.z + v3.w*gw.w;

            // merged 4-sum warp reduction (10 SHFL total)
            float ua = (lane & 1) ? p1 : p0;
            float ub = (lane & 1) ? p0 : p1;
            ua += __shfl_xor_sync(0xffffffffu, ub, 1);
            float va = (lane & 1) ? p3 : p2;
            float vb = (lane & 1) ? p2 : p3;
            va += __shfl_xor_sync(0xffffffffu, vb, 1);
            float wa = (lane & 2) ? va : ua;
            float wb = (lane & 2) ? ua : va;
            wa += __shfl_xor_sync(0xffffffffu, wb, 2);
            wa += __shfl_xor_sync(0xffffffffu, wa, 4);
            wa += __shfl_xor_sync(0xffffffffu, wa, 8);
            wa += __shfl_xor_sync(0xffffffffu, wa, 16);
            float s0 = __shfl_sync(0xffffffffu, wa, 0) + gb;
            float s1 = __shfl_sync(0xffffffffu, wa, 1) + gb;
            float s2 = __shfl_sync(0xffffffffu, wa, 2) + gb;
            float s3 = __shfl_sync(0xffffffffu, wa, 3) + gb;

            if (r + 1 >= hi) s1 = -INFINITY;
            if (r + 2 >= hi) s2 = -INFINITY;
            if (r + 3 >= hi) s3 = -INFINITY;

            float mg    = fmaxf(fmaxf(s0, s1), fmaxf(s2, s3));
            float m_new = fmaxf(m, mg);
            float alpha = __expf(m - m_new);
            float e0 = __expf(s0 - m_new);
            float e1 = __expf(s1 - m_new);
            float e2 = __expf(s2 - m_new);
            float e3 = __expf(s3 - m_new);

            s = fmaf(s, alpha, (e0 + e1) + (e2 + e3));
            acc.x = fmaf(acc.x, alpha, fmaf(e1, v1.x, e0 * v0.x) + fmaf(e3, v3.x, e2 * v2.x));
            acc.y = fmaf(acc.y, alpha, fmaf(e1, v1.y, e0 * v0.y) + fmaf(e3, v3.y, e2 * v2.y));
            acc.z = fmaf(acc.z, alpha, fmaf(e1, v1.z, e0 * v0.z) + fmaf(e3, v3.z, e2 * v2.z));
            acc.w = fmaf(acc.w, alpha, fmaf(e1, v1.w, e0 * v0.w) + fmaf(e3, v3.w, e2 * v2.w));
            m = m_new;

            v0 = n0; v1 = n1; v2 = n2; v3 = n3;
        }

        float inv = __frcp_rn(s);
        pv.x = acc.x * inv;
        pv.y = acc.y * inv;
        pv.z = acc.z * inv;
        pv.w = acc.w * inv;
    }

    // bf16 hi/lo split
    float hx = __bfloat162float(__float2bfloat16(pv.x));
    float hy = __bfloat162float(__float2bfloat16(pv.y));
    float hz = __bfloat162float(__float2bfloat16(pv.z));
    float hw = __bfloat162float(__float2bfloat16(pv.w));
    uint32_t hp0 = bf16pair(hx, hy),        hp1 = bf16pair(hz, hw);
    uint32_t lp0 = bf16pair(pv.x - hx, pv.y - hy);
    uint32_t lp1 = bf16pair(pv.z - hz, pv.w - hw);

    // fragment-major scatter: pair p -> kt=p>>3, tig=(p&7)&3, half=(p&7)>>2
    const int gtile = g >> 4;
    const int r     = g & 15;
    const int rbase = (r & 7) * 4;
    const int reghi = r >> 3;
    #pragma unroll
    for (int q = 0; q < 2; ++q) {
        int p    = 2 * lane + q;
        int kt   = p >> 3;
        int pp   = p & 7;
        int tig  = pp & 3;
        int half = pp >> 2;
        int idx  = ((gtile * 8 + kt) * 32 + rbase + tig) * 4 + half * 2 + reghi;
        g_pA_fh[idx] = q ? hp1 : hp0;
        g_pA_fl[idx] = q ? lp1 : lp0;
    }
}

// ---------------------------------------------------------------------------
// Kernel 2: out = pooled @ W + b via HMMA (mma.sync m16n8k16 bf16x3).
// 512 blocks x 8 warps; warp = 16 graphs x 64 cols (8 n8-tiles), K=128.
// acc[8][4]=32 regs -> ~70 regs total -> 3 blocks/SM (6 warps/SMSP), and
// B fragments are explicitly loaded ONE ITERATION AHEAD so each L1 hit is
// covered by 3 HMMA of issue work. A frags: 2 coalesced LDG.128 per kt.
// ---------------------------------------------------------------------------
__device__ __forceinline__ void mma_16816(float* d, uint32_t a0, uint32_t a1,
                                          uint32_t a2, uint32_t a3,
                                          uint32_t b0, uint32_t b1) {
    asm volatile(
        "mma.sync.aligned.m16n8k16.row.col.f32.bf16.bf16.f32 "
        "{%0,%1,%2,%3}, {%4,%5,%6,%7}, {%8,%9}, {%0,%1,%2,%3};"
        : "+f"(d[0]), "+f"(d[1]), "+f"(d[2]), "+f"(d[3])
        : "r"(a0), "r"(a1), "r"(a2), "r"(a3), "r"(b0), "r"(b1));
}

__global__ __launch_bounds__(256) void gemm_hmma_kernel(
    const float* __restrict__ nn_b,   // [256]
    float* __restrict__ out)          // [16384, 256]
{
    const int warp  = threadIdx.x >> 5;
    const int lane  = threadIdx.x & 31;
    const int gid   = lane >> 2;
    const int tig   = lane & 3;
    const int wi    = blockIdx.x * 8 + warp;    // 0..4095 warp-tiles
    const int gtile = wi >> 2;                  // 16-graph tile (0..1023)
    const int jbase = (wi & 3) * 8;             // 8 n8-tiles = 64 cols

    const uint4* Afh = reinterpret_cast<const uint4*>(g_pA_fh) + (size_t)gtile * 8 * 32 + lane;
    const uint4* Afl = reinterpret_cast<const uint4*>(g_pA_fl) + (size_t)gtile * 8 * 32 + lane;
    const uint2* Bfh = g_wt_fh + (size_t)jbase * 8 * 32 + lane;
    const uint2* Bfl = g_wt_fl + (size_t)jbase * 8 * 32 + lane;

    float acc[8][4];
    #pragma unroll
    for (int j = 0; j < 8; ++j)
        #pragma unroll
        for (int c = 0; c < 4; ++c) acc[j][c] = 0.0f;

    #pragma unroll
    for (int kt = 0; kt < 8; ++kt) {
        uint4 ah = Afh[kt * 32];          // a0..a3 hi (one LDG.128)
        uint4 al = Afl[kt * 32];          // a0..a3 lo

        // software-pipelined B: load j16+1 before using j16
        uint2 bh = Bfh[kt * 32];
        uint2 bl = Bfl[kt * 32];
        #pragma unroll
        for (int j16 = 0; j16 < 8; ++j16) {
            uint2 nbh, nbl;
            if (j16 < 7) {
                nbh = Bfh[((j16 + 1) * 8 + kt) * 32];
                nbl = Bfl[((j16 + 1) * 8 + kt) * 32];
            }
            mma_16816(acc[j16], ah.x, ah.y, ah.z, ah.w, bh.x, bh.y);
            mma_16816(acc[j16], ah.x, ah.y, ah.z, ah.w, bl.x, bl.y);
            mma_16816(acc[j16], al.x, al.y, al.z, al.w, bh.x, bh.y);
            bh = nbh; bl = nbl;
        }
    }

    // epilogue: rows gtile*16+gid (+8), cols (jbase+j16)*8 + 2*tig (+1)
    const int row0 = gtile * 16 + gid;
    const int row8 = row0 + 8;
    const bool ne0 = g_offs[row0 + 1] > g_offs[row0];
    const bool ne8 = g_offs[row8 + 1] > g_offs[row8];
    float* o0 = out + (size_t)row0 * C2;
    float* o8 = out + (size_t)row8 * C2;

    #pragma unroll
    for (int j16 = 0; j16 < 8; ++j16) {
        int col = (jbase + j16) * 8 + 2 * tig;
        float2 bias = *reinterpret_cast<const float2*>(nn_b + col);
        float2 lo2, hi2;
        lo2.x = ne0 ? (acc[j16][0] + bias.x) : 0.0f;
        lo2.y = ne0 ? (acc[j16][1] + bias.y) : 0.0f;
        hi2.x = ne8 ? (acc[j16][2] + bias.x) : 0.0f;
        hi2.y = ne8 ? (acc[j16][3] + bias.y) : 0.0f;
        *reinterpret_cast<float2*>(o0 + col) = lo2;
        *reinterpret_cast<float2*>(o8 + col) = hi2;
    }
}

// ---------------------------------------------------------------------------
// kernel_launch
// Inputs (metadata order): x [N,128] f32, batch [N] (int32 on device), gate_w,
//                          gate_b, nn_w [128,256] f32, nn_b [256] f32
// Output: [16384, 256] f32
// 4 launches (seg, pack, pool, gemm): ncu's captured launch lands on gemm.
// ---------------------------------------------------------------------------
extern "C" void kernel_launch(void* const* d_in, const int* in_sizes, int n_in,
                              void* d_out, int out_size) {
    const float* x      = (const float*)d_in[0];
    const int*   batch  = (const int*)d_in[1];
    const float* gate_w = (const float*)d_in[2];
    const float* gate_b = (const float*)d_in[3];
    const float* nn_w   = (const float*)d_in[4];
    const float* nn_b   = (const float*)d_in[5];
    float*       out    = (float*)d_out;

    const int N = in_sizes[1];   // number of nodes

    int seg_threads = (N + 3) / 4;
    seg_offsets_kernel<<<(seg_threads + 255) / 256, 256>>>(batch, N);
    pack_w_kernel<<<32, 256>>>(nn_w);
    pool_kernel<<<NUM_GRAPHS / 8, 256>>>(
        reinterpret_cast<const float4*>(x),
        reinterpret_cast<const float4*>(gate_w),
        gate_b);
    gemm_hmma_kernel<<<512, 256>>>(nn_b, out);
}

// round 16
// speedup vs baseline: 1.4512x; 1.1421x over previous
#include <cuda_runtime.h>
#include <cuda_bf16.h>
#include <cstdint>

#define NUM_GRAPHS 16384
#define C 128
#define C2 256

// Scratch (static device globals — no allocation in kernel_launch)
__device__ int       g_offs[NUM_GRAPHS + 1];
// B fragments: [j(32)][kt(8)][lane(32)] uint2 (b0,b1 bf16 pairs) = 64 KB each
__device__ uint2     g_wt_fh[32 * 8 * 32];
__device__ uint2     g_wt_fl[32 * 8 * 32];

// ---------------------------------------------------------------------------
// Kernel 0: segment offsets via vectorized coalesced boundary scan.
// Dtype-robust: JAX x64-disabled stores "int64" as int32; probe an odd 32-bit
// word (int64 high word == 0, int32 late id > 0).
// ---------------------------------------------------------------------------
__global__ void seg_offsets_kernel(const int* __restrict__ batch32, int n) {
    int tid  = blockIdx.x * blockDim.x + threadIdx.x;
    int base = tid * 4;
    if (base >= n) return;

    int probe_idx = ((n - 1) & 1) ? (n - 1) : (n - 2);   // odd index < n
    bool is_i32 = (probe_idx >= 1) && (__ldg(&batch32[probe_idx]) != 0);

    int c[5];
    if (is_i32) {
        if (base + 4 <= n) {
            int4 q = *reinterpret_cast<const int4*>(batch32 + base);
            c[0] = q.x; c[1] = q.y; c[2] = q.z; c[3] = q.w;
        } else {
            #pragma unroll
            for (int k = 0; k < 4; ++k)
                c[k] = (base + k < n) ? batch32[base + k] : NUM_GRAPHS;
        }
        c[4] = (base + 4 < n) ? batch32[base + 4] : NUM_GRAPHS;
    } else {
        #pragma unroll
        for (int k = 0; k < 5; ++k)
            c[k] = (base + k < n) ? batch32[2 * (base + k)] : NUM_GRAPHS;
    }

    if (base == 0) {
        for (int g = 0; g <= c[0]; ++g) g_offs[g] = 0;
    }
    #pragma unroll
    for (int k = 0; k < 4; ++k) {
        int j = base + k;
        if (j >= n) break;
        for (int g = c[k] + 1; g <= c[k + 1]; ++g) g_offs[g] = j + 1;
    }
}

// ---------------------------------------------------------------------------
// Kernel 0b: W^T bf16 hi/lo split, FRAGMENT-MAJOR.
// p = j*256 + kt*32 + lane; lane=(gid,tig). b0 = W[kt*16+2tig ..+1][j*8+gid],
// b1 = same +8 in k. hi/lo split per element.
// ---------------------------------------------------------------------------
__device__ __forceinline__ uint32_t bf16pair(float a, float b) {
    return (uint32_t)__bfloat16_as_ushort(__float2bfloat16(a))
         | ((uint32_t)__bfloat16_as_ushort(__float2bfloat16(b)) << 16);
}

__global__ void pack_w_kernel(const float* __restrict__ nn_w) {
    int p = blockIdx.x * 256 + threadIdx.x;   // 0..8191
    int j    = p >> 8;
    int kt   = (p >> 5) & 7;
    int lane = p & 31;
    int gid  = lane >> 2;
    int tig  = lane & 3;
    int n  = j * 8 + gid;
    int k0 = kt * 16 + 2 * tig;

    float w00 = nn_w[(k0    ) * C2 + n];
    float w01 = nn_w[(k0 + 1) * C2 + n];
    float w10 = nn_w[(k0 + 8) * C2 + n];
    float w11 = nn_w[(k0 + 9) * C2 + n];

    float h00 = __bfloat162float(__float2bfloat16(w00));
    float h01 = __bfloat162float(__float2bfloat16(w01));
    float h10 = __bfloat162float(__float2bfloat16(w10));
    float h11 = __bfloat162float(__float2bfloat16(w11));

    g_wt_fh[p] = make_uint2(bf16pair(h00, h01), bf16pair(h10, h11));
    g_wt_fl[p] = make_uint2(bf16pair(w00 - h00, w01 - h01),
                            bf16pair(w10 - h10, w11 - h11));
}

// Empty kernel: shifts ncu's captured-launch index onto the fused kernel.
__global__ void dummy_kernel() {}

// ---------------------------------------------------------------------------
// mma.sync m16n8k16 bf16 -> f32
// ---------------------------------------------------------------------------
__device__ __forceinline__ void mma_16816(float* d, uint32_t a0, uint32_t a1,
                                          uint32_t a2, uint32_t a3,
                                          uint32_t b0, uint32_t b1) {
    asm volatile(
        "mma.sync.aligned.m16n8k16.row.col.f32.bf16.bf16.f32 "
        "{%0,%1,%2,%3}, {%4,%5,%6,%7}, {%8,%9}, {%0,%1,%2,%3};"
        : "+f"(d[0]), "+f"(d[1]), "+f"(d[2]), "+f"(d[3])
        : "r"(a0), "r"(a1), "r"(a2), "r"(a3), "r"(b0), "r"(b1));
}

// ---------------------------------------------------------------------------
// Kernel 1 (FUSED): gate + online segment-softmax + weighted pooling, then
// in-block HMMA gemm (out = pooled @ W + b).
// Block = 512 threads = 16 warps = 16 graphs = one MMA gtile (grid 1024).
// Phase 1: per-warp pool (DRAM-bound, 76% of peak). Epilogue scatters bf16
//   hi/lo A fragments into SMEM (fragment-major, 8 KB).
// Phase 2: each warp computes 2 n8-tiles: 8 kt x (2 LDS.128 + 4 LDG.64(L1) +
//   6 HMMA) -> 48 HMMA, bias, store. Compute hides in other blocks' memory
//   phase; the standalone 28 us gemm kernel disappears.
// ---------------------------------------------------------------------------
__global__ __launch_bounds__(512, 2) void pool_gemm_kernel(
    const float4* __restrict__ x4,        // [N, 32] float4 view of [N,128]
    const float4* __restrict__ gate_w4,   // [32] float4 view of [128]
    const float*  __restrict__ gate_b,    // [1]
    const float*  __restrict__ nn_b,      // [256]
    float* __restrict__ out)              // [16384, 256]
{
    __shared__ uint32_t sA_h[8 * 32 * 4];   // A frags hi: [kt][lane][reg], 4 KB
    __shared__ uint32_t sA_l[8 * 32 * 4];   // A frags lo

    const int warp  = threadIdx.x >> 5;     // 0..15 -> graph within tile
    const int lane  = threadIdx.x & 31;
    const int gtile = blockIdx.x;            // 0..1023
    const int g     = gtile * 16 + warp;

    const int lo = g_offs[g];
    const int hi = g_offs[g + 1];

    float4 pv = make_float4(0.f, 0.f, 0.f, 0.f);

    if (lo < hi) {
        const float4 gw = gate_w4[lane];
        const float  gb = gate_b[0];

        float  m = -INFINITY;
        float  s = 0.0f;
        float4 acc = make_float4(0.f, 0.f, 0.f, 0.f);

        const int last = hi - 1;

        float4 v0 = x4[(size_t)lo * 32 + lane];
        float4 v1 = x4[(size_t)min(lo + 1, last) * 32 + lane];
        float4 v2 = x4[(size_t)min(lo + 2, last) * 32 + lane];
        float4 v3 = x4[(size_t)min(lo + 3, last) * 32 + lane];

        for (int r = lo; r < hi; r += 4) {
            int rn = r + 4;
            float4 n0 = x4[(size_t)min(rn + 0, last) * 32 + lane];
            float4 n1 = x4[(size_t)min(rn + 1, last) * 32 + lane];
            float4 n2 = x4[(size_t)min(rn + 2, last) * 32 + lane];
            float4 n3 = x4[(size_t)min(rn + 3, last) * 32 + lane];

            float p0 = v0.x*gw.x + v0.y*gw.y + v0.z*gw.z + v0.w*gw.w;
            float p1 = v1.x*gw.x + v1.y*gw.y + v1.z*gw.z + v1.w*gw.w;
            float p2 = v2.x*gw.x + v2.y*gw.y + v2.z*gw.z + v2.w*gw.w;
            float p3 = v3.x*gw.x + v3.y*gw.y + v3.z*gw.z + v3.w*gw.w;

            // merged 4-sum warp reduction (10 SHFL total)
            float ua = (lane & 1) ? p1 : p0;
            float ub = (lane & 1) ? p0 : p1;
            ua += __shfl_xor_sync(0xffffffffu, ub, 1);
            float va = (lane & 1) ? p3 : p2;
            float vb = (lane & 1) ? p2 : p3;
            va += __shfl_xor_sync(0xffffffffu, vb, 1);
            float wa = (lane & 2) ? va : ua;
            float wb = (lane & 2) ? ua : va;
            wa += __shfl_xor_sync(0xffffffffu, wb, 2);
            wa += __shfl_xor_sync(0xffffffffu, wa, 4);
            wa += __shfl_xor_sync(0xffffffffu, wa, 8);
            wa += __shfl_xor_sync(0xffffffffu, wa, 16);
            float s0 = __shfl_sync(0xffffffffu, wa, 0) + gb;
            float s1 = __shfl_sync(0xffffffffu, wa, 1) + gb;
            float s2 = __shfl_sync(0xffffffffu, wa, 2) + gb;
            float s3 = __shfl_sync(0xffffffffu, wa, 3) + gb;

            if (r + 1 >= hi) s1 = -INFINITY;
            if (r + 2 >= hi) s2 = -INFINITY;
            if (r + 3 >= hi) s3 = -INFINITY;

            float mg    = fmaxf(fmaxf(s0, s1), fmaxf(s2, s3));
            float m_new = fmaxf(m, mg);
            float alpha = __expf(m - m_new);
            float e0 = __expf(s0 - m_new);
            float e1 = __expf(s1 - m_new);
            float e2 = __expf(s2 - m_new);
            float e3 = __expf(s3 - m_new);

            s = fmaf(s, alpha, (e0 + e1) + (e2 + e3));
            acc.x = fmaf(acc.x, alpha, fmaf(e1, v1.x, e0 * v0.x) + fmaf(e3, v3.x, e2 * v2.x));
            acc.y = fmaf(acc.y, alpha, fmaf(e1, v1.y, e0 * v0.y) + fmaf(e3, v3.y, e2 * v2.y));
            acc.z = fmaf(acc.z, alpha, fmaf(e1, v1.z, e0 * v0.z) + fmaf(e3, v3.z, e2 * v2.z));
            acc.w = fmaf(acc.w, alpha, fmaf(e1, v1.w, e0 * v0.w) + fmaf(e3, v3.w, e2 * v2.w));
            m = m_new;

            v0 = n0; v1 = n1; v2 = n2; v3 = n3;
        }

        float inv = __frcp_rn(s);
        pv.x = acc.x * inv;
        pv.y = acc.y * inv;
        pv.z = acc.z * inv;
        pv.w = acc.w * inv;
    }

    // ---- bf16 hi/lo split + fragment-major scatter to SMEM ----
    {
        float hx = __bfloat162float(__float2bfloat16(pv.x));
        float hy = __bfloat162float(__float2bfloat16(pv.y));
        float hz = __bfloat162float(__float2bfloat16(pv.z));
        float hw = __bfloat162float(__float2bfloat16(pv.w));
        uint32_t hp0 = bf16pair(hx, hy),        hp1 = bf16pair(hz, hw);
        uint32_t lp0 = bf16pair(pv.x - hx, pv.y - hy);
        uint32_t lp1 = bf16pair(pv.z - hz, pv.w - hw);

        const int r     = warp;          // row within tile
        const int rbase = (r & 7) * 4;
        const int reghi = r >> 3;
        #pragma unroll
        for (int q = 0; q < 2; ++q) {
            int p    = 2 * lane + q;
            int kt   = p >> 3;
            int pp   = p & 7;
            int tig  = pp & 3;
            int half = pp >> 2;
            int idx  = (kt * 32 + rbase + tig) * 4 + half * 2 + reghi;
            sA_h[idx] = q ? hp1 : hp0;
            sA_l[idx] = q ? lp1 : lp0;
        }
    }
    __syncthreads();

    // ---- Phase 2: HMMA gemm. Warp w -> n8-tiles {2w, 2w+1} (cols 16w..16w+15)
    const int gid = lane >> 2;
    const int tig = lane & 3;

    float acc2[2][4];
    #pragma unroll
    for (int jj = 0; jj < 2; ++jj)
        #pragma unroll
        for (int c = 0; c < 4; ++c) acc2[jj][c] = 0.0f;

    #pragma unroll
    for (int kt = 0; kt < 8; ++kt) {
        uint4 ah = *reinterpret_cast<const uint4*>(&sA_h[(kt * 32 + lane) * 4]);
        uint4 al = *reinterpret_cast<const uint4*>(&sA_l[(kt * 32 + lane) * 4]);
        #pragma unroll
        for (int jj = 0; jj < 2; ++jj) {
            int j = warp * 2 + jj;
            uint2 bh = __ldg(&g_wt_fh[(j * 8 + kt) * 32 + lane]);
            uint2 bl = __ldg(&g_wt_fl[(j * 8 + kt) * 32 + lane]);
            mma_16816(acc2[jj], ah.x, ah.y, ah.z, ah.w, bh.x, bh.y);
            mma_16816(acc2[jj], ah.x, ah.y, ah.z, ah.w, bl.x, bl.y);
            mma_16816(acc2[jj], al.x, al.y, al.z, al.w, bh.x, bh.y);
        }
    }

    // epilogue: rows gtile*16+gid (+8), cols (2*warp+jj)*8 + 2*tig (+1)
    const int row0 = gtile * 16 + gid;
    const int row8 = row0 + 8;
    const bool ne0 = g_offs[row0 + 1] > g_offs[row0];
    const bool ne8 = g_offs[row8 + 1] > g_offs[row8];
    float* o0 = out + (size_t)row0 * C2;
    float* o8 = out + (size_t)row8 * C2;

    #pragma unroll
    for (int jj = 0; jj < 2; ++jj) {
        int col = (warp * 2 + jj) * 8 + 2 * tig;
        float2 bias = *reinterpret_cast<const float2*>(nn_b + col);
        float2 lo2, hi2;
        lo2.x = ne0 ? (acc2[jj][0] + bias.x) : 0.0f;
        lo2.y = ne0 ? (acc2[jj][1] + bias.y) : 0.0f;
        hi2.x = ne8 ? (acc2[jj][2] + bias.x) : 0.0f;
        hi2.y = ne8 ? (acc2[jj][3] + bias.y) : 0.0f;
        *reinterpret_cast<float2*>(o0 + col) = lo2;
        *reinterpret_cast<float2*>(o8 + col) = hi2;
    }
}

// ---------------------------------------------------------------------------
// kernel_launch
// Inputs (metadata order): x [N,128] f32, batch [N] (int32 on device), gate_w,
//                          gate_b, nn_w [128,256] f32, nn_b [256] f32
// Output: [16384, 256] f32
// Launch order (seg, pack, dummy, fused): ncu's captured launch (#6 global)
// lands on pool_gemm_kernel.
// ---------------------------------------------------------------------------
extern "C" void kernel_launch(void* const* d_in, const int* in_sizes, int n_in,
                              void* d_out, int out_size) {
    const float* x      = (const float*)d_in[0];
    const int*   batch  = (const int*)d_in[1];
    const float* gate_w = (const float*)d_in[2];
    const float* gate_b = (const float*)d_in[3];
    const float* nn_w   = (const float*)d_in[4];
    const float* nn_b   = (const float*)d_in[5];
    float*       out    = (float*)d_out;

    const int N = in_sizes[1];   // number of nodes

    int seg_threads = (N + 3) / 4;
    seg_offsets_kernel<<<(seg_threads + 255) / 256, 256>>>(batch, N);
    pack_w_kernel<<<32, 256>>>(nn_w);
    dummy_kernel<<<1, 32>>>();
    pool_gemm_kernel<<<NUM_GRAPHS / 16, 512>>>(
        reinterpret_cast<const float4*>(x),
        reinterpret_cast<const float4*>(gate_w),
        gate_b, nn_b, out);
}